// round 9
// baseline (speedup 1.0000x reference)
#include <cuda_runtime.h>
#include <cuda_bf16.h>
#include <cuda_fp16.h>
#include <cstdint>
#include <math.h>

// Problem constants (fixed by the reference)
#define NNODES 100000
#define NEDGES 1600000
#define DFEAT  128
#define HEADS  4
#define DHEAD  32
#define NEG_SLOPE 0.2f

// ---------------- scratch (static device globals; no allocations) ------------
__device__ int    g_deg[NNODES];
__device__ int    g_cursor[NNODES];
__device__ int    g_off[NNODES];
__device__ int    g_total;
__device__ int    g_csr[NEDGES];
__device__ float  g_w[(size_t)NEDGES * HEADS];      // spill path for deg>32 nodes
__device__ float  g_bufA[(size_t)NNODES * DFEAT];   // GEMM output h (fp32)
__device__ float  g_bufB[(size_t)NNODES * DFEAT];   // layer-1 aggregated + relu
__device__ float  g_es[NNODES * HEADS];
__device__ float  g_ed[NNODES * HEADS];

// ---------------- CSR build --------------------------------------------------
__global__ void count_kernel(const int* __restrict__ dst, int e) {
    int i = blockIdx.x * blockDim.x + threadIdx.x;
    if (i < e) atomicAdd(&g_deg[dst[i]], 1);
}

// Unordered CSR offsets: warp inclusive scan + one atomicAdd per warp.
__global__ void offsets_kernel(int n) {
    int i = blockIdx.x * blockDim.x + threadIdx.x;
    int lane = threadIdx.x & 31;
    int d = (i < n) ? g_deg[i] : 0;
    int inc = d;
#pragma unroll
    for (int o = 1; o < 32; o <<= 1) {
        int t = __shfl_up_sync(0xffffffffu, inc, o);
        if (lane >= o) inc += t;
    }
    int warpTot = __shfl_sync(0xffffffffu, inc, 31);
    int base = 0;
    if (lane == 31) base = atomicAdd(&g_total, warpTot);
    base = __shfl_sync(0xffffffffu, base, 31);
    int off = base + inc - d;
    if (i < n) { g_off[i] = off; g_cursor[i] = off; }
}

__global__ void scatter_kernel(const int* __restrict__ src,
                               const int* __restrict__ dst, int e) {
    int i = blockIdx.x * blockDim.x + threadIdx.x;
    if (i < e) {
        int d = dst[i];
        int slot = atomicAdd(&g_cursor[d], 1);
        g_csr[slot] = src[i];
    }
}

// ---------------- fused GEMM + attention-logit epilogue ----------------------
// out[M,128] = X[M,128] @ W[128,128], fp16 tensor cores (m16n8k16), fp32 accum.
// X staged as half pairs [64 rows][136 halves]; W staged TRANSPOSED Wt[n][k]
// so B fragments' (k,k+1) pairs are one 32-bit LDS.
// Row stride 68 uint32 -> bank = (4g+t): conflict-free fragment loads.
// ~52 KB smem -> 3 CTAs/SM (24 warps/SM).
#define XS2 68     // uint32 stride per X row
#define WT2 68     // uint32 stride per Wt row
#define GEMM_SMEM ((64 * XS2 + 128 * WT2) * 4)

__device__ __forceinline__ uint32_t h2_bits(__half2 h) {
    uint32_t u;
    *(__half2*)&u = h;
    return u;
}

__device__ __forceinline__ void mma_f16(float* d, const uint32_t* a, const uint32_t* b) {
    asm volatile(
        "mma.sync.aligned.m16n8k16.row.col.f32.f16.f16.f32 "
        "{%0,%1,%2,%3}, {%4,%5,%6,%7}, {%8,%9}, {%0,%1,%2,%3};\n"
        : "+f"(d[0]), "+f"(d[1]), "+f"(d[2]), "+f"(d[3])
        : "r"(a[0]), "r"(a[1]), "r"(a[2]), "r"(a[3]),
          "r"(b[0]), "r"(b[1]));
}

__global__ __launch_bounds__(256, 3)
void gemm_fused_kernel(const float* __restrict__ X, const float* __restrict__ W,
                       const float* __restrict__ asrc, const float* __restrict__ adst,
                       float* __restrict__ out, float* __restrict__ es,
                       float* __restrict__ ed, int M) {
    extern __shared__ float sm[];
    uint32_t* Xs = (uint32_t*)sm;                 // [64][XS2] packed half2
    uint32_t* Wt = (uint32_t*)sm + 64 * XS2;      // [128 n][WT2] packed half2 (k pairs)
    __half*   WtH = (__half*)Wt;
    int tid = threadIdx.x;
    int rowBase = blockIdx.x * 64;

    // Stage X tile as packed halves (zero-pad OOB rows)
#pragma unroll 2
    for (int i = tid; i < 64 * 32; i += 256) {
        int r = i >> 5, c4 = (i & 31) << 2;          // 4 floats per iter
        int gr = rowBase + r;
        float4 v = make_float4(0.f, 0.f, 0.f, 0.f);
        if (gr < M) v = *(const float4*)&X[(size_t)gr * 128 + c4];
        uint2 u;
        u.x = h2_bits(__float22half2_rn(make_float2(v.x, v.y)));
        u.y = h2_bits(__float22half2_rn(make_float2(v.z, v.w)));
        *(uint2*)&Xs[r * XS2 + (c4 >> 1)] = u;
    }
    // Stage W transposed: Wt[n][k] halves (read coalesced along n, scatter to smem)
#pragma unroll 4
    for (int i = tid; i < 128 * 32; i += 256) {
        int k = i >> 5, n4 = (i & 31) << 2;
        float4 v = *(const float4*)&W[(size_t)k * 128 + n4];
        WtH[(n4 + 0) * (WT2 * 2) + k] = __float2half_rn(v.x);
        WtH[(n4 + 1) * (WT2 * 2) + k] = __float2half_rn(v.y);
        WtH[(n4 + 2) * (WT2 * 2) + k] = __float2half_rn(v.z);
        WtH[(n4 + 3) * (WT2 * 2) + k] = __float2half_rn(v.w);
    }
    __syncthreads();

    int lane = tid & 31, warp = tid >> 5;
    int g = lane >> 2, t = lane & 3;
    int wm = (warp & 1) * 32;
    int wn = (warp >> 1) * 32;
    int head = warp >> 1;

    float acc[2][4][4];
#pragma unroll
    for (int mb = 0; mb < 2; mb++)
#pragma unroll
        for (int nb = 0; nb < 4; nb++)
#pragma unroll
            for (int i = 0; i < 4; i++) acc[mb][nb][i] = 0.f;

#pragma unroll
    for (int kp = 0; kp < 64; kp += 8) {     // 8 k16-chunks; kp = pair index base
        uint32_t a[2][4];
#pragma unroll
        for (int mb = 0; mb < 2; mb++) {
            int r0 = wm + mb * 16;
            a[mb][0] = Xs[(r0 + g) * XS2 + kp + t];
            a[mb][1] = Xs[(r0 + g + 8) * XS2 + kp + t];
            a[mb][2] = Xs[(r0 + g) * XS2 + kp + t + 4];
            a[mb][3] = Xs[(r0 + g + 8) * XS2 + kp + t + 4];
        }
        uint32_t b[4][2];
#pragma unroll
        for (int nb = 0; nb < 4; nb++) {
            int n = wn + nb * 8 + g;
            b[nb][0] = Wt[n * WT2 + kp + t];
            b[nb][1] = Wt[n * WT2 + kp + t + 4];
        }
#pragma unroll
        for (int mb = 0; mb < 2; mb++)
#pragma unroll
            for (int nb = 0; nb < 4; nb++)
                mma_f16(acc[mb][nb], a[mb], b[nb]);
    }

    // Store h and accumulate per-thread attention-logit partials.
    float ps[2][2], pd[2][2];   // [mb][rowhalf]; this warp's cols = one head
#pragma unroll
    for (int a = 0; a < 2; a++)
#pragma unroll
        for (int b = 0; b < 2; b++) { ps[a][b] = 0.f; pd[a][b] = 0.f; }

#pragma unroll
    for (int mb = 0; mb < 2; mb++)
#pragma unroll
        for (int nb = 0; nb < 4; nb++) {
            int col = wn + nb * 8 + 2 * t;
            float as0 = __ldg(&asrc[col]), as1 = __ldg(&asrc[col + 1]);
            float ad0 = __ldg(&adst[col]), ad1 = __ldg(&adst[col + 1]);
            float c0 = acc[mb][nb][0], c1 = acc[mb][nb][1];
            float c2 = acc[mb][nb][2], c3 = acc[mb][nb][3];
            ps[mb][0] += c0 * as0 + c1 * as1;
            ps[mb][1] += c2 * as0 + c3 * as1;
            pd[mb][0] += c0 * ad0 + c1 * ad1;
            pd[mb][1] += c2 * ad0 + c3 * ad1;

            int row0 = rowBase + wm + mb * 16 + g;
            if (row0 < M) {
                float2 v; v.x = c0; v.y = c1;
                *(float2*)&out[(size_t)row0 * 128 + col] = v;
            }
            int row1 = row0 + 8;
            if (row1 < M) {
                float2 v; v.x = c2; v.y = c3;
                *(float2*)&out[(size_t)row1 * 128 + col] = v;
            }
        }

    __syncthreads();                 // done reading Xs — reuse as esd stage
    float* esd = sm;                 // [64 rows][4 heads][2 (src,dst)]
#pragma unroll
    for (int mb = 0; mb < 2; mb++)
#pragma unroll
        for (int half = 0; half < 2; half++) {
            float vs = ps[mb][half];
            float vd = pd[mb][half];
            vs += __shfl_xor_sync(0xffffffffu, vs, 1);
            vs += __shfl_xor_sync(0xffffffffu, vs, 2);
            vd += __shfl_xor_sync(0xffffffffu, vd, 1);
            vd += __shfl_xor_sync(0xffffffffu, vd, 2);
            if (t == 0) {
                int row = wm + mb * 16 + half * 8 + g;
                esd[row * 8 + head * 2 + 0] = vs;
                esd[row * 8 + head * 2 + 1] = vd;
            }
        }
    __syncthreads();
    if (tid < 64) {
        int grow = rowBase + tid;
        if (grow < M) {
            float4 vs, vd;
            vs.x = esd[tid * 8 + 0]; vd.x = esd[tid * 8 + 1];
            vs.y = esd[tid * 8 + 2]; vd.y = esd[tid * 8 + 3];
            vs.z = esd[tid * 8 + 4]; vd.z = esd[tid * 8 + 5];
            vs.w = esd[tid * 8 + 6]; vd.w = esd[tid * 8 + 7];
            *(float4*)&es[grow * 4] = vs;
            *(float4*)&ed[grow * 4] = vd;
        }
    }
}

// ---------------- aggregation: one warp per destination node -----------------
__device__ __forceinline__ float warp_sum(float v) {
#pragma unroll
    for (int o = 16; o; o >>= 1) v += __shfl_xor_sync(0xffffffffu, v, o);
    return v;
}

__device__ __forceinline__ float warp_max(float v) {
#pragma unroll
    for (int o = 16; o; o >>= 1) v = fmaxf(v, __shfl_xor_sync(0xffffffffu, v, o));
    return v;
}

__device__ __forceinline__ float lrelu(float x) {
    return x > 0.f ? x : NEG_SLOPE * x;
}

// Layout: lane owns features [4*lane, 4*lane+4) -> all in head (lane>>3).
// mode 0: out = relu(agg + bias); mode 1: out = log_softmax(agg + bias)
__global__ __launch_bounds__(256)
void aggregate_kernel(const float* __restrict__ h, const float* __restrict__ es,
                      const float* __restrict__ ed, const float* __restrict__ bias,
                      float* __restrict__ out, int n, int mode) {
    __shared__ int   sm_s[8][32];
    __shared__ float sm_a[8][32][4];
    int wi = threadIdx.x >> 5;
    int w = blockIdx.x * 8 + wi;
    int lane = threadIdx.x & 31;
    if (w >= n) return;
    int beg = g_off[w];
    int deg = g_deg[w];
    int end = beg + deg;
    float4 edv = *(const float4*)&ed[w * 4];
    int head = lane >> 3;

    float acc0 = 0.f, acc1 = 0.f, acc2 = 0.f, acc3 = 0.f;

    if (deg <= 32) {
        int j = beg + lane;
        int s = 0;
        float c0 = -1e30f, c1 = -1e30f, c2 = -1e30f, c3 = -1e30f;
        if (j < end) {
            s = g_csr[j];
            float4 e = *(const float4*)&es[s * 4];
            c0 = lrelu(e.x + edv.x); c1 = lrelu(e.y + edv.y);
            c2 = lrelu(e.z + edv.z); c3 = lrelu(e.w + edv.w);
        }
        float m0 = warp_max(c0), m1 = warp_max(c1);
        float m2 = warp_max(c2), m3 = warp_max(c3);
        float w0 = 0.f, w1 = 0.f, w2 = 0.f, w3 = 0.f;
        if (j < end) {
            w0 = __expf(c0 - m0); w1 = __expf(c1 - m1);
            w2 = __expf(c2 - m2); w3 = __expf(c3 - m3);
        }
        float z0 = warp_sum(w0), z1 = warp_sum(w1);
        float z2 = warp_sum(w2), z3 = warp_sum(w3);
        float i0 = (z0 > 0.f) ? 1.f / z0 : 0.f;
        float i1 = (z1 > 0.f) ? 1.f / z1 : 0.f;
        float i2 = (z2 > 0.f) ? 1.f / z2 : 0.f;
        float i3 = (z3 > 0.f) ? 1.f / z3 : 0.f;

        sm_s[wi][lane] = s;
        *(float4*)&sm_a[wi][lane][0] = make_float4(w0 * i0, w1 * i1, w2 * i2, w3 * i3);
        __syncwarp();
#pragma unroll 4
        for (int k = 0; k < deg; k++) {
            int   sk = sm_s[wi][k];
            float b  = sm_a[wi][k][head];
            float4 hv = *(const float4*)&h[(size_t)sk * 128 + lane * 4];
            acc0 = fmaf(b, hv.x, acc0); acc1 = fmaf(b, hv.y, acc1);
            acc2 = fmaf(b, hv.z, acc2); acc3 = fmaf(b, hv.w, acc3);
        }
    } else {
        float m0 = -1e30f, m1 = -1e30f, m2 = -1e30f, m3 = -1e30f;
        for (int j = beg + lane; j < end; j += 32) {
            int s = g_csr[j];
            float4 e = *(const float4*)&es[s * 4];
            m0 = fmaxf(m0, lrelu(e.x + edv.x)); m1 = fmaxf(m1, lrelu(e.y + edv.y));
            m2 = fmaxf(m2, lrelu(e.z + edv.z)); m3 = fmaxf(m3, lrelu(e.w + edv.w));
        }
        m0 = warp_max(m0); m1 = warp_max(m1); m2 = warp_max(m2); m3 = warp_max(m3);
        float z0 = 0.f, z1 = 0.f, z2 = 0.f, z3 = 0.f;
        for (int j = beg + lane; j < end; j += 32) {
            int s = g_csr[j];
            float4 e = *(const float4*)&es[s * 4];
            float w0 = __expf(lrelu(e.x + edv.x) - m0);
            float w1 = __expf(lrelu(e.y + edv.y) - m1);
            float w2 = __expf(lrelu(e.z + edv.z) - m2);
            float w3 = __expf(lrelu(e.w + edv.w) - m3);
            *(float4*)&g_w[(size_t)j * 4] = make_float4(w0, w1, w2, w3);
            z0 += w0; z1 += w1; z2 += w2; z3 += w3;
        }
        z0 = warp_sum(z0); z1 = warp_sum(z1); z2 = warp_sum(z2); z3 = warp_sum(z3);
        float i0 = (z0 > 0.f) ? 1.f / z0 : 0.f;
        float i1 = (z1 > 0.f) ? 1.f / z1 : 0.f;
        float i2 = (z2 > 0.f) ? 1.f / z2 : 0.f;
        float i3 = (z3 > 0.f) ? 1.f / z3 : 0.f;

        for (int j0 = beg; j0 < end; j0 += 32) {
            int j = j0 + lane;
            __syncwarp();
            if (j < end) {
                sm_s[wi][lane] = g_csr[j];
                float4 wv = *(const float4*)&g_w[(size_t)j * 4];
                *(float4*)&sm_a[wi][lane][0] =
                    make_float4(wv.x * i0, wv.y * i1, wv.z * i2, wv.w * i3);
            }
            __syncwarp();
            int cnt = min(32, end - j0);
#pragma unroll 4
            for (int k = 0; k < cnt; k++) {
                int   sk = sm_s[wi][k];
                float b  = sm_a[wi][k][head];
                float4 hv = *(const float4*)&h[(size_t)sk * 128 + lane * 4];
                acc0 = fmaf(b, hv.x, acc0); acc1 = fmaf(b, hv.y, acc1);
                acc2 = fmaf(b, hv.z, acc2); acc3 = fmaf(b, hv.w, acc3);
            }
        }
    }

    float4 bv = *(const float4*)&bias[lane * 4];
    acc0 += bv.x; acc1 += bv.y; acc2 += bv.z; acc3 += bv.w;

    float* op = out + (size_t)w * 128 + lane * 4;
    if (mode == 0) {
        float4 v;
        v.x = fmaxf(acc0, 0.f); v.y = fmaxf(acc1, 0.f);
        v.z = fmaxf(acc2, 0.f); v.w = fmaxf(acc3, 0.f);
        *(float4*)op = v;
    } else {
        float mx = fmaxf(fmaxf(acc0, acc1), fmaxf(acc2, acc3));
        mx = warp_max(mx);
        float se = __expf(acc0 - mx) + __expf(acc1 - mx) +
                   __expf(acc2 - mx) + __expf(acc3 - mx);
        se = warp_sum(se);
        float lse = mx + logf(se);
        float4 v;
        v.x = acc0 - lse; v.y = acc1 - lse; v.z = acc2 - lse; v.w = acc3 - lse;
        *(float4*)op = v;
    }
}

// ---------------- launch -----------------------------------------------------
extern "C" void kernel_launch(void* const* d_in, const int* in_sizes, int n_in,
                              void* d_out, int out_size) {
    const int*   edge  = (const int*)d_in[0];     // [2, E]
    const float* feats = (const float*)d_in[1];   // [N, 128]
    const float* W1    = (const float*)d_in[2];
    const float* a1s   = (const float*)d_in[3];
    const float* a1d   = (const float*)d_in[4];
    const float* b1    = (const float*)d_in[5];
    const float* W2    = (const float*)d_in[6];
    const float* a2s   = (const float*)d_in[7];
    const float* a2d   = (const float*)d_in[8];
    const float* b2    = (const float*)d_in[9];
    float* out = (float*)d_out;

    const int E = in_sizes[0] / 2;
    const int N = in_sizes[1] / DFEAT;
    const int* src = edge;
    const int* dst = edge + E;

    float *bufA, *bufB, *es, *ed;
    void *degP, *totP;
    cudaGetSymbolAddress((void**)&bufA, g_bufA);
    cudaGetSymbolAddress((void**)&bufB, g_bufB);
    cudaGetSymbolAddress((void**)&es, g_es);
    cudaGetSymbolAddress((void**)&ed, g_ed);
    cudaGetSymbolAddress(&degP, g_deg);
    cudaGetSymbolAddress(&totP, g_total);

    cudaFuncSetAttribute(gemm_fused_kernel,
                         cudaFuncAttributeMaxDynamicSharedMemorySize, GEMM_SMEM);

    // CSR build (unordered node ranges; no scan needed)
    cudaMemsetAsync(degP, 0, N * sizeof(int));
    cudaMemsetAsync(totP, 0, sizeof(int));
    count_kernel<<<(E + 255) / 256, 256>>>(dst, E);
    offsets_kernel<<<(N + 255) / 256, 256>>>(N);
    scatter_kernel<<<(E + 255) / 256, 256>>>(src, dst, E);

    const int gemmGrid = (N + 63) / 64;
    const int aggGrid  = (N + 7) / 8;

    // Layer 1
    gemm_fused_kernel<<<gemmGrid, 256, GEMM_SMEM>>>(feats, W1, a1s, a1d, bufA, es, ed, N);
    aggregate_kernel<<<aggGrid, 256>>>(bufA, es, ed, b1, bufB, N, 0);

    // Layer 2
    gemm_fused_kernel<<<gemmGrid, 256, GEMM_SMEM>>>(bufB, W2, a2s, a2d, bufA, es, ed, N);
    aggregate_kernel<<<aggGrid, 256>>>(bufA, es, ed, b2, out, N, 1);
}

// round 10
// speedup vs baseline: 1.3022x; 1.3022x over previous
#include <cuda_runtime.h>
#include <cuda_bf16.h>
#include <cuda_fp16.h>
#include <cstdint>
#include <math.h>

// Problem constants (fixed by the reference)
#define NNODES 100000
#define NEDGES 1600000
#define DFEAT  128
#define HEADS  4
#define DHEAD  32
#define NEG_SLOPE 0.2f

// ---------------- scratch (static device globals; no allocations) ------------
__device__ int    g_deg[NNODES];
__device__ int    g_cursor[NNODES];
__device__ int    g_off[NNODES];
__device__ int    g_total;
__device__ int    g_csr[NEDGES];
__device__ float  g_w[(size_t)NEDGES * HEADS];      // spill path for deg>32 nodes
__device__ float  g_bufA[(size_t)NNODES * DFEAT];   // GEMM output h (fp32)
__device__ float  g_bufB[(size_t)NNODES * DFEAT];   // layer-1 aggregated + relu
__device__ float  g_es[NNODES * HEADS];
__device__ float  g_ed[NNODES * HEADS];

// ---------------- CSR build --------------------------------------------------
__global__ void count_kernel(const int* __restrict__ dst, int e) {
    int i = blockIdx.x * blockDim.x + threadIdx.x;
    if (i < e) atomicAdd(&g_deg[dst[i]], 1);
}

// Unordered CSR offsets: warp inclusive scan + one atomicAdd per warp.
__global__ void offsets_kernel(int n) {
    int i = blockIdx.x * blockDim.x + threadIdx.x;
    int lane = threadIdx.x & 31;
    int d = (i < n) ? g_deg[i] : 0;
    int inc = d;
#pragma unroll
    for (int o = 1; o < 32; o <<= 1) {
        int t = __shfl_up_sync(0xffffffffu, inc, o);
        if (lane >= o) inc += t;
    }
    int warpTot = __shfl_sync(0xffffffffu, inc, 31);
    int base = 0;
    if (lane == 31) base = atomicAdd(&g_total, warpTot);
    base = __shfl_sync(0xffffffffu, base, 31);
    int off = base + inc - d;
    if (i < n) { g_off[i] = off; g_cursor[i] = off; }
}

__global__ void scatter_kernel(const int* __restrict__ src,
                               const int* __restrict__ dst, int e) {
    int i = blockIdx.x * blockDim.x + threadIdx.x;
    if (i < e) {
        int d = dst[i];
        int slot = atomicAdd(&g_cursor[d], 1);
        g_csr[slot] = src[i];
    }
}

// ---------------- fused GEMM + attention-logit epilogue ----------------------
// out[M,128] = X[M,128] @ W[128,128], fp16 tensor cores (m16n8k16), fp32 accum.
// X staged row-major packed half2 [64][XS2]; W staged K-MAJOR packed half2
// [128 k][WK2] (coalesced, conflict-free staging). Fragments loaded via
// ldmatrix (.x4 for A, .x4.trans for B) — conflict-free (stride 68 uint32).
// ~52 KB smem -> 3 CTAs/SM.
#define XS2 68     // uint32 stride per X row
#define WK2 68     // uint32 stride per Wk row (k index)
#define GEMM_SMEM ((64 * XS2 + 128 * WK2) * 4)

__device__ __forceinline__ uint32_t h2_bits(__half2 h) {
    uint32_t u;
    *(__half2*)&u = h;
    return u;
}

__device__ __forceinline__ void ldsm_x4(uint32_t& r0, uint32_t& r1,
                                        uint32_t& r2, uint32_t& r3, uint32_t addr) {
    asm volatile("ldmatrix.sync.aligned.m8n8.x4.shared.b16 {%0,%1,%2,%3}, [%4];"
                 : "=r"(r0), "=r"(r1), "=r"(r2), "=r"(r3) : "r"(addr));
}

__device__ __forceinline__ void ldsm_x4_trans(uint32_t& r0, uint32_t& r1,
                                              uint32_t& r2, uint32_t& r3, uint32_t addr) {
    asm volatile("ldmatrix.sync.aligned.m8n8.x4.trans.shared.b16 {%0,%1,%2,%3}, [%4];"
                 : "=r"(r0), "=r"(r1), "=r"(r2), "=r"(r3) : "r"(addr));
}

__device__ __forceinline__ void mma_f16(float* d, const uint32_t* a, const uint32_t* b) {
    asm volatile(
        "mma.sync.aligned.m16n8k16.row.col.f32.f16.f16.f32 "
        "{%0,%1,%2,%3}, {%4,%5,%6,%7}, {%8,%9}, {%0,%1,%2,%3};\n"
        : "+f"(d[0]), "+f"(d[1]), "+f"(d[2]), "+f"(d[3])
        : "r"(a[0]), "r"(a[1]), "r"(a[2]), "r"(a[3]),
          "r"(b[0]), "r"(b[1]));
}

__global__ __launch_bounds__(256, 3)
void gemm_fused_kernel(const float* __restrict__ X, const float* __restrict__ W,
                       const float* __restrict__ asrc, const float* __restrict__ adst,
                       float* __restrict__ out, float* __restrict__ es,
                       float* __restrict__ ed, int M) {
    extern __shared__ float sm[];
    uint32_t* Xs = (uint32_t*)sm;                 // [64][XS2] packed half2
    uint32_t* Wk = (uint32_t*)sm + 64 * XS2;      // [128 k][WK2] packed half2 along n
    int tid = threadIdx.x;
    int rowBase = blockIdx.x * 64;

    // Stage X tile as packed halves (zero-pad OOB rows) — coalesced, conflict-free
#pragma unroll 2
    for (int i = tid; i < 64 * 32; i += 256) {
        int r = i >> 5, c4 = (i & 31) << 2;          // 4 floats per iter
        int gr = rowBase + r;
        float4 v = make_float4(0.f, 0.f, 0.f, 0.f);
        if (gr < M) v = *(const float4*)&X[(size_t)gr * 128 + c4];
        uint2 u;
        u.x = h2_bits(__float22half2_rn(make_float2(v.x, v.y)));
        u.y = h2_bits(__float22half2_rn(make_float2(v.z, v.w)));
        *(uint2*)&Xs[r * XS2 + (c4 >> 1)] = u;
    }
    // Stage W k-major as packed halves — coalesced, conflict-free
#pragma unroll 4
    for (int i = tid; i < 128 * 32; i += 256) {
        int k = i >> 5, n4 = (i & 31) << 2;
        float4 v = *(const float4*)&W[(size_t)k * 128 + n4];
        uint2 u;
        u.x = h2_bits(__float22half2_rn(make_float2(v.x, v.y)));
        u.y = h2_bits(__float22half2_rn(make_float2(v.z, v.w)));
        *(uint2*)&Wk[k * WK2 + (n4 >> 1)] = u;
    }
    __syncthreads();

    int lane = tid & 31, warp = tid >> 5;
    int g = lane >> 2, t = lane & 3;
    int wm = (warp & 1) * 32;
    int wn = (warp >> 1) * 32;
    int head = warp >> 1;

    uint32_t smemU = (uint32_t)__cvta_generic_to_shared(sm);

    // ldmatrix base addresses (bytes)
    // A (x4): t0-7 rows0-7@k0 | t8-15 rows8-15@k0 | t16-23 rows0-7@k8 | t24-31 rows8-15@k8
    int aRow = (lane & 15);
    int aKoff = ((lane >> 4) & 1) * 16;              // +8 halves = 16 bytes
    uint32_t addrA0 = smemU + (uint32_t)((wm + aRow) * XS2 * 4 + aKoff);
    uint32_t addrA1 = smemU + (uint32_t)((wm + 16 + aRow) * XS2 * 4 + aKoff);
    // B (x4.trans): t0-7 k0-7@slice0 | t8-15 k8-15@slice0 | t16-23 k0-7@slice1 | t24-31 k8-15@slice1
    int bKrow = (lane & 7) + ((lane >> 3) & 1) * 8;
    uint32_t wkBase = smemU + 64 * XS2 * 4;
    int bNsl0 = wn + ((lane >> 4) & 1) * 8;          // slices 0,8  (nb 0,1)
    int bNsl1 = wn + 16 + ((lane >> 4) & 1) * 8;     // slices 16,24 (nb 2,3)
    uint32_t addrB0 = wkBase + (uint32_t)(bKrow * WK2 * 4 + bNsl0 * 2);
    uint32_t addrB1 = wkBase + (uint32_t)(bKrow * WK2 * 4 + bNsl1 * 2);

    float acc[2][4][4];
#pragma unroll
    for (int mb = 0; mb < 2; mb++)
#pragma unroll
        for (int nb = 0; nb < 4; nb++)
#pragma unroll
            for (int i = 0; i < 4; i++) acc[mb][nb][i] = 0.f;

#pragma unroll
    for (int chunk = 0; chunk < 8; chunk++) {        // k16 chunks
        uint32_t a[2][4], b[4][2];
        ldsm_x4(a[0][0], a[0][1], a[0][2], a[0][3], addrA0);
        ldsm_x4(a[1][0], a[1][1], a[1][2], a[1][3], addrA1);
        ldsm_x4_trans(b[0][0], b[0][1], b[1][0], b[1][1], addrB0);
        ldsm_x4_trans(b[2][0], b[2][1], b[3][0], b[3][1], addrB1);
        addrA0 += 32; addrA1 += 32;                  // +16 halves along k
        addrB0 += 16 * WK2 * 4; addrB1 += 16 * WK2 * 4;  // +16 k-rows
#pragma unroll
        for (int mb = 0; mb < 2; mb++)
#pragma unroll
            for (int nb = 0; nb < 4; nb++)
                mma_f16(acc[mb][nb], a[mb], b[nb]);
    }

    // Store h and accumulate per-thread attention-logit partials.
    float ps[2][2], pd[2][2];   // [mb][rowhalf]; this warp's cols = one head
#pragma unroll
    for (int a = 0; a < 2; a++)
#pragma unroll
        for (int b = 0; b < 2; b++) { ps[a][b] = 0.f; pd[a][b] = 0.f; }

#pragma unroll
    for (int mb = 0; mb < 2; mb++)
#pragma unroll
        for (int nb = 0; nb < 4; nb++) {
            int col = wn + nb * 8 + 2 * t;
            float as0 = __ldg(&asrc[col]), as1 = __ldg(&asrc[col + 1]);
            float ad0 = __ldg(&adst[col]), ad1 = __ldg(&adst[col + 1]);
            float c0 = acc[mb][nb][0], c1 = acc[mb][nb][1];
            float c2 = acc[mb][nb][2], c3 = acc[mb][nb][3];
            ps[mb][0] += c0 * as0 + c1 * as1;
            ps[mb][1] += c2 * as0 + c3 * as1;
            pd[mb][0] += c0 * ad0 + c1 * ad1;
            pd[mb][1] += c2 * ad0 + c3 * ad1;

            int row0 = rowBase + wm + mb * 16 + g;
            if (row0 < M) {
                float2 v; v.x = c0; v.y = c1;
                *(float2*)&out[(size_t)row0 * 128 + col] = v;
            }
            int row1 = row0 + 8;
            if (row1 < M) {
                float2 v; v.x = c2; v.y = c3;
                *(float2*)&out[(size_t)row1 * 128 + col] = v;
            }
        }

    __syncthreads();                 // done reading Xs — reuse as esd stage
    float* esd = sm;                 // [64 rows][4 heads][2 (src,dst)]
#pragma unroll
    for (int mb = 0; mb < 2; mb++)
#pragma unroll
        for (int half = 0; half < 2; half++) {
            float vs = ps[mb][half];
            float vd = pd[mb][half];
            vs += __shfl_xor_sync(0xffffffffu, vs, 1);
            vs += __shfl_xor_sync(0xffffffffu, vs, 2);
            vd += __shfl_xor_sync(0xffffffffu, vd, 1);
            vd += __shfl_xor_sync(0xffffffffu, vd, 2);
            if (t == 0) {
                int row = wm + mb * 16 + half * 8 + g;
                esd[row * 8 + head * 2 + 0] = vs;
                esd[row * 8 + head * 2 + 1] = vd;
            }
        }
    __syncthreads();
    if (tid < 64) {
        int grow = rowBase + tid;
        if (grow < M) {
            float4 vs, vd;
            vs.x = esd[tid * 8 + 0]; vd.x = esd[tid * 8 + 1];
            vs.y = esd[tid * 8 + 2]; vd.y = esd[tid * 8 + 3];
            vs.z = esd[tid * 8 + 4]; vd.z = esd[tid * 8 + 5];
            vs.w = esd[tid * 8 + 6]; vd.w = esd[tid * 8 + 7];
            *(float4*)&es[grow * 4] = vs;
            *(float4*)&ed[grow * 4] = vd;
        }
    }
}

// ---------------- aggregation: one warp per destination node -----------------
__device__ __forceinline__ float warp_sum(float v) {
#pragma unroll
    for (int o = 16; o; o >>= 1) v += __shfl_xor_sync(0xffffffffu, v, o);
    return v;
}

__device__ __forceinline__ float warp_max(float v) {
#pragma unroll
    for (int o = 16; o; o >>= 1) v = fmaxf(v, __shfl_xor_sync(0xffffffffu, v, o));
    return v;
}

__device__ __forceinline__ float lrelu(float x) {
    return x > 0.f ? x : NEG_SLOPE * x;
}

// Layout: lane owns features [4*lane, 4*lane+4) -> all in head (lane>>3).
// mode 0: out = relu(agg + bias); mode 1: out = log_softmax(agg + bias)
__global__ __launch_bounds__(256)
void aggregate_kernel(const float* __restrict__ h, const float* __restrict__ es,
                      const float* __restrict__ ed, const float* __restrict__ bias,
                      float* __restrict__ out, int n, int mode) {
    __shared__ int   sm_s[8][32];
    __shared__ float sm_a[8][32][4];
    int wi = threadIdx.x >> 5;
    int w = blockIdx.x * 8 + wi;
    int lane = threadIdx.x & 31;
    if (w >= n) return;
    int beg = g_off[w];
    int deg = g_deg[w];
    int end = beg + deg;
    float4 edv = *(const float4*)&ed[w * 4];
    int head = lane >> 3;

    float acc0 = 0.f, acc1 = 0.f, acc2 = 0.f, acc3 = 0.f;

    if (deg <= 32) {
        int j = beg + lane;
        int s = 0;
        float c0 = -1e30f, c1 = -1e30f, c2 = -1e30f, c3 = -1e30f;
        if (j < end) {
            s = g_csr[j];
            float4 e = *(const float4*)&es[s * 4];
            c0 = lrelu(e.x + edv.x); c1 = lrelu(e.y + edv.y);
            c2 = lrelu(e.z + edv.z); c3 = lrelu(e.w + edv.w);
        }
        float m0 = warp_max(c0), m1 = warp_max(c1);
        float m2 = warp_max(c2), m3 = warp_max(c3);
        float w0 = 0.f, w1 = 0.f, w2 = 0.f, w3 = 0.f;
        if (j < end) {
            w0 = __expf(c0 - m0); w1 = __expf(c1 - m1);
            w2 = __expf(c2 - m2); w3 = __expf(c3 - m3);
        }
        float z0 = warp_sum(w0), z1 = warp_sum(w1);
        float z2 = warp_sum(w2), z3 = warp_sum(w3);
        float i0 = (z0 > 0.f) ? 1.f / z0 : 0.f;
        float i1 = (z1 > 0.f) ? 1.f / z1 : 0.f;
        float i2 = (z2 > 0.f) ? 1.f / z2 : 0.f;
        float i3 = (z3 > 0.f) ? 1.f / z3 : 0.f;

        sm_s[wi][lane] = s;
        *(float4*)&sm_a[wi][lane][0] = make_float4(w0 * i0, w1 * i1, w2 * i2, w3 * i3);
        __syncwarp();
#pragma unroll 4
        for (int k = 0; k < deg; k++) {
            int   sk = sm_s[wi][k];
            float b  = sm_a[wi][k][head];
            float4 hv = *(const float4*)&h[(size_t)sk * 128 + lane * 4];
            acc0 = fmaf(b, hv.x, acc0); acc1 = fmaf(b, hv.y, acc1);
            acc2 = fmaf(b, hv.z, acc2); acc3 = fmaf(b, hv.w, acc3);
        }
    } else {
        float m0 = -1e30f, m1 = -1e30f, m2 = -1e30f, m3 = -1e30f;
        for (int j = beg + lane; j < end; j += 32) {
            int s = g_csr[j];
            float4 e = *(const float4*)&es[s * 4];
            m0 = fmaxf(m0, lrelu(e.x + edv.x)); m1 = fmaxf(m1, lrelu(e.y + edv.y));
            m2 = fmaxf(m2, lrelu(e.z + edv.z)); m3 = fmaxf(m3, lrelu(e.w + edv.w));
        }
        m0 = warp_max(m0); m1 = warp_max(m1); m2 = warp_max(m2); m3 = warp_max(m3);
        float z0 = 0.f, z1 = 0.f, z2 = 0.f, z3 = 0.f;
        for (int j = beg + lane; j < end; j += 32) {
            int s = g_csr[j];
            float4 e = *(const float4*)&es[s * 4];
            float w0 = __expf(lrelu(e.x + edv.x) - m0);
            float w1 = __expf(lrelu(e.y + edv.y) - m1);
            float w2 = __expf(lrelu(e.z + edv.z) - m2);
            float w3 = __expf(lrelu(e.w + edv.w) - m3);
            *(float4*)&g_w[(size_t)j * 4] = make_float4(w0, w1, w2, w3);
            z0 += w0; z1 += w1; z2 += w2; z3 += w3;
        }
        z0 = warp_sum(z0); z1 = warp_sum(z1); z2 = warp_sum(z2); z3 = warp_sum(z3);
        float i0 = (z0 > 0.f) ? 1.f / z0 : 0.f;
        float i1 = (z1 > 0.f) ? 1.f / z1 : 0.f;
        float i2 = (z2 > 0.f) ? 1.f / z2 : 0.f;
        float i3 = (z3 > 0.f) ? 1.f / z3 : 0.f;

        for (int j0 = beg; j0 < end; j0 += 32) {
            int j = j0 + lane;
            __syncwarp();
            if (j < end) {
                sm_s[wi][lane] = g_csr[j];
                float4 wv = *(const float4*)&g_w[(size_t)j * 4];
                *(float4*)&sm_a[wi][lane][0] =
                    make_float4(wv.x * i0, wv.y * i1, wv.z * i2, wv.w * i3);
            }
            __syncwarp();
            int cnt = min(32, end - j0);
#pragma unroll 4
            for (int k = 0; k < cnt; k++) {
                int   sk = sm_s[wi][k];
                float b  = sm_a[wi][k][head];
                float4 hv = *(const float4*)&h[(size_t)sk * 128 + lane * 4];
                acc0 = fmaf(b, hv.x, acc0); acc1 = fmaf(b, hv.y, acc1);
                acc2 = fmaf(b, hv.z, acc2); acc3 = fmaf(b, hv.w, acc3);
            }
        }
    }

    float4 bv = *(const float4*)&bias[lane * 4];
    acc0 += bv.x; acc1 += bv.y; acc2 += bv.z; acc3 += bv.w;

    float* op = out + (size_t)w * 128 + lane * 4;
    if (mode == 0) {
        float4 v;
        v.x = fmaxf(acc0, 0.f); v.y = fmaxf(acc1, 0.f);
        v.z = fmaxf(acc2, 0.f); v.w = fmaxf(acc3, 0.f);
        *(float4*)op = v;
    } else {
        float mx = fmaxf(fmaxf(acc0, acc1), fmaxf(acc2, acc3));
        mx = warp_max(mx);
        float se = __expf(acc0 - mx) + __expf(acc1 - mx) +
                   __expf(acc2 - mx) + __expf(acc3 - mx);
        se = warp_sum(se);
        float lse = mx + logf(se);
        float4 v;
        v.x = acc0 - lse; v.y = acc1 - lse; v.z = acc2 - lse; v.w = acc3 - lse;
        *(float4*)op = v;
    }
}

// ---------------- launch -----------------------------------------------------
extern "C" void kernel_launch(void* const* d_in, const int* in_sizes, int n_in,
                              void* d_out, int out_size) {
    const int*   edge  = (const int*)d_in[0];     // [2, E]
    const float* feats = (const float*)d_in[1];   // [N, 128]
    const float* W1    = (const float*)d_in[2];
    const float* a1s   = (const float*)d_in[3];
    const float* a1d   = (const float*)d_in[4];
    const float* b1    = (const float*)d_in[5];
    const float* W2    = (const float*)d_in[6];
    const float* a2s   = (const float*)d_in[7];
    const float* a2d   = (const float*)d_in[8];
    const float* b2    = (const float*)d_in[9];
    float* out = (float*)d_out;

    const int E = in_sizes[0] / 2;
    const int N = in_sizes[1] / DFEAT;
    const int* src = edge;
    const int* dst = edge + E;

    float *bufA, *bufB, *es, *ed;
    void *degP, *totP;
    cudaGetSymbolAddress((void**)&bufA, g_bufA);
    cudaGetSymbolAddress((void**)&bufB, g_bufB);
    cudaGetSymbolAddress((void**)&es, g_es);
    cudaGetSymbolAddress((void**)&ed, g_ed);
    cudaGetSymbolAddress(&degP, g_deg);
    cudaGetSymbolAddress(&totP, g_total);

    cudaFuncSetAttribute(gemm_fused_kernel,
                         cudaFuncAttributeMaxDynamicSharedMemorySize, GEMM_SMEM);

    // CSR build (unordered node ranges; no scan needed)
    cudaMemsetAsync(degP, 0, N * sizeof(int));
    cudaMemsetAsync(totP, 0, sizeof(int));
    count_kernel<<<(E + 255) / 256, 256>>>(dst, E);
    offsets_kernel<<<(N + 255) / 256, 256>>>(N);
    scatter_kernel<<<(E + 255) / 256, 256>>>(src, dst, E);

    const int gemmGrid = (N + 63) / 64;
    const int aggGrid  = (N + 7) / 8;

    // Layer 1
    gemm_fused_kernel<<<gemmGrid, 256, GEMM_SMEM>>>(feats, W1, a1s, a1d, bufA, es, ed, N);
    aggregate_kernel<<<aggGrid, 256>>>(bufA, es, ed, b1, bufB, N, 0);

    // Layer 2
    gemm_fused_kernel<<<gemmGrid, 256, GEMM_SMEM>>>(bufB, W2, a2s, a2d, bufA, es, ed, N);
    aggregate_kernel<<<aggGrid, 256>>>(bufA, es, ed, b2, out, N, 1);
}